// round 4
// baseline (speedup 1.0000x reference)
#include <cuda_runtime.h>
#include <cuda_bf16.h>

// GaussianSmoother: out[b,n] = sum_t x[b,t,n] * k[t]
// x: [B=64, T=2048, N=1024] fp32.
//
// R1: Gaussian truncated to +/-128 taps (6.4 sigma, tail ~1e-10) ->
//     64.3 MiB traffic. Z = sigma*sqrt(2pi) compile-time constant.
// R2: 4-way tap split + smem reduce -> occ 83%, DRAM 52%.
// R3: float4 loads (LDG.128) -> 4x bytes per scoreboard slot; 16-way
//     tap split (16 taps/thread) keeps thread count at 262144.

#define B_DIM 64
#define T_DIM 2048
#define N_DIM 1024
#define CENTER 1024
#define W 128
#define TAPS (2 * W + 1)   // 257
#define SIGMA 20.0f

// 1 / (sigma * sqrt(2*pi)) for sigma = 20
#define INV_Z 0.019947114020071634f

#define BLOCK_THREADS 512
#define VEC_PER_BLOCK 32          // 32 float4 = 128 n-values per block
#define GROUPS 16
#define TAPS_PER_GROUP 16         // 16*16 = 256; group 15 takes tap 256
#define N_VEC (N_DIM / 4)         // 256 float4 per (b, t) row

__global__ __launch_bounds__(BLOCK_THREADS) void gaussian_smooth_kernel(
    const float4* __restrict__ x, float4* __restrict__ out)
{
    __shared__ float k[TAPS];
    __shared__ float4 partial[GROUPS - 1][VEC_PER_BLOCK];

    int tid = threadIdx.x;

    // Build normalized Gaussian weights (once per block).
    for (int i = tid; i < TAPS; i += BLOCK_THREADS) {
        float d = (float)(i - W) * (1.0f / SIGMA);
        k[i] = expf(-0.5f * d * d) * INV_Z;
    }
    __syncthreads();

    int nl = tid & (VEC_PER_BLOCK - 1);   // vec4 lane within block
    int g  = tid >> 5;                    // tap-group 0..15

    int vidx = blockIdx.x * VEC_PER_BLOCK + nl;  // global vec4 index [0, 16384)
    int b  = vidx >> 8;                    // vidx / N_VEC
    int nv = vidx & (N_VEC - 1);           // vidx % N_VEC

    int t0 = g * TAPS_PER_GROUP;

    const float4* p = x + (size_t)b * T_DIM * N_VEC
                        + (size_t)(CENTER - W + t0) * N_VEC
                        + nv;

    float4 acc = make_float4(0.f, 0.f, 0.f, 0.f);
    #pragma unroll 8
    for (int i = 0; i < TAPS_PER_GROUP; i++) {
        float4 v = p[(size_t)i * N_VEC];
        float  w = k[t0 + i];
        acc.x += v.x * w;
        acc.y += v.y * w;
        acc.z += v.z * w;
        acc.w += v.w * w;
    }
    // leftover tap (257 = 16*16 + 1) handled by the last group
    if (g == GROUPS - 1) {
        float4 v = p[(size_t)TAPS_PER_GROUP * N_VEC];
        float  w = k[TAPS - 1];
        acc.x += v.x * w;
        acc.y += v.y * w;
        acc.z += v.z * w;
        acc.w += v.w * w;
    }

    if (g > 0) {
        partial[g - 1][nl] = acc;
    }
    __syncthreads();

    if (g == 0) {
        #pragma unroll
        for (int j = 0; j < GROUPS - 1; j++) {
            float4 v = partial[j][nl];
            acc.x += v.x;
            acc.y += v.y;
            acc.z += v.z;
            acc.w += v.w;
        }
        out[vidx] = acc;
    }
}

extern "C" void kernel_launch(void* const* d_in, const int* in_sizes, int n_in,
                              void* d_out, int out_size)
{
    const float4* x = (const float4*)d_in[0];
    float4* out = (float4*)d_out;

    const int blocks = (B_DIM * N_DIM / 4) / VEC_PER_BLOCK;   // 512

    gaussian_smooth_kernel<<<blocks, BLOCK_THREADS>>>(x, out);
}

// round 5
// speedup vs baseline: 1.2694x; 1.2694x over previous
#include <cuda_runtime.h>
#include <cuda_bf16.h>

// GaussianSmoother: out[b,n] = sum_t x[b,t,n] * k[t]
// x: [B=64, T=2048, N=1024] fp32.
//
// R1: Gaussian truncation + analytic normalization Z = sigma*sqrt(2pi).
// R2: tap-split across thread groups + smem reduce (occupancy fix).
// R3: float4 loads (LDG.128).
// R4 finding: timed run already moves 6.1 TB/s -> at the memory ceiling.
//     Remaining lever is TRAFFIC: tighten window W 128 -> 88 (4.4 sigma,
//     tail mass erfc(4.4/sqrt2) = 1.1e-5, worst-element rel err ~4e-5,
//     25x under the 1e-3 threshold). 257 -> 177 taps, 31% less HBM.

#define B_DIM 64
#define T_DIM 2048
#define N_DIM 1024
#define CENTER 1024
#define W 88
#define TAPS (2 * W + 1)   // 177
#define SIGMA 20.0f

// 1 / (sigma * sqrt(2*pi)) for sigma = 20  (Z over full 2048 taps equals
// sigma*sqrt(2pi) to ~e^-7800 by Poisson summation)
#define INV_Z 0.019947114020071634f

#define BLOCK_THREADS 512
#define VEC_PER_BLOCK 32          // 32 float4 = 128 n-values per block
#define GROUPS 16
#define TAPS_PER_GROUP 11         // 16*11 = 176; group 15 takes tap 176
#define N_VEC (N_DIM / 4)         // 256 float4 per (b, t) row

__global__ __launch_bounds__(BLOCK_THREADS) void gaussian_smooth_kernel(
    const float4* __restrict__ x, float4* __restrict__ out)
{
    __shared__ float k[TAPS];
    __shared__ float4 partial[GROUPS - 1][VEC_PER_BLOCK];

    int tid = threadIdx.x;

    // Build normalized Gaussian weights (once per block).
    for (int i = tid; i < TAPS; i += BLOCK_THREADS) {
        float d = (float)(i - W) * (1.0f / SIGMA);
        k[i] = expf(-0.5f * d * d) * INV_Z;
    }
    __syncthreads();

    int nl = tid & (VEC_PER_BLOCK - 1);   // vec4 lane within block
    int g  = tid >> 5;                    // tap-group 0..15 (one warp each)

    int vidx = blockIdx.x * VEC_PER_BLOCK + nl;  // global vec4 index [0, 16384)
    int b  = vidx >> 8;                    // vidx / N_VEC
    int nv = vidx & (N_VEC - 1);           // vidx % N_VEC

    int t0 = g * TAPS_PER_GROUP;

    const float4* p = x + (size_t)b * T_DIM * N_VEC
                        + (size_t)(CENTER - W + t0) * N_VEC
                        + nv;

    float4 acc = make_float4(0.f, 0.f, 0.f, 0.f);
    #pragma unroll
    for (int i = 0; i < TAPS_PER_GROUP; i++) {
        float4 v = p[(size_t)i * N_VEC];
        float  w = k[t0 + i];
        acc.x += v.x * w;
        acc.y += v.y * w;
        acc.z += v.z * w;
        acc.w += v.w * w;
    }
    // leftover tap (177 = 16*11 + 1) handled by the last group
    if (g == GROUPS - 1) {
        float4 v = p[(size_t)TAPS_PER_GROUP * N_VEC];
        float  w = k[TAPS - 1];
        acc.x += v.x * w;
        acc.y += v.y * w;
        acc.z += v.z * w;
        acc.w += v.w * w;
    }

    if (g > 0) {
        partial[g - 1][nl] = acc;
    }
    __syncthreads();

    if (g == 0) {
        #pragma unroll
        for (int j = 0; j < GROUPS - 1; j++) {
            float4 v = partial[j][nl];
            acc.x += v.x;
            acc.y += v.y;
            acc.z += v.z;
            acc.w += v.w;
        }
        out[vidx] = acc;
    }
}

extern "C" void kernel_launch(void* const* d_in, const int* in_sizes, int n_in,
                              void* d_out, int out_size)
{
    const float4* x = (const float4*)d_in[0];
    float4* out = (float4*)d_out;

    const int blocks = (B_DIM * N_DIM / 4) / VEC_PER_BLOCK;   // 512

    gaussian_smooth_kernel<<<blocks, BLOCK_THREADS>>>(x, out);
}